// round 15
// baseline (speedup 1.0000x reference)
#include <cuda_runtime.h>
#include <cuda_fp16.h>
#include <cstdint>

// Problem dims (fixed by reference setup_inputs)
#define MM   8192      // B*S
#define NN   4096      // D_OUT
#define KK   4096      // D_IN
#define RR   16
#define LORA_SCALING 2.0f

// ---------------------------------------------------------------------------
// Device scratch (static __device__ arrays — no runtime allocation)
// ---------------------------------------------------------------------------
__device__ __half g_xh[(size_t)MM * KK];   // 64 MB: x rounded to fp16
__device__ __half g_wh[(size_t)NN * KK];   // 32 MB: fused dequant+LoRA weight, fp16

// ---------------------------------------------------------------------------
// Helpers (base PTX only — sm_103 target has no 'a'-feature instructions)
// ---------------------------------------------------------------------------
__device__ __forceinline__ uint32_t smem_u32(const void* p) {
    uint32_t a;
    asm("{ .reg .u64 t; cvta.to.shared.u64 t, %1; cvt.u32.u64 %0, t; }"
        : "=r"(a) : "l"(p));
    return a;
}

#define CP_ASYNC16(dst_u32, src_ptr) \
    asm volatile("cp.async.cg.shared.global [%0], [%1], 16;\n" :: "r"(dst_u32), "l"(src_ptr))
#define CP_COMMIT()   asm volatile("cp.async.commit_group;\n" ::)
#define CP_WAIT(n)    asm volatile("cp.async.wait_group %0;\n" :: "n"(n))

#define LDMATRIX_X4(r0, r1, r2, r3, addr)                                     \
    asm volatile("ldmatrix.sync.aligned.m8n8.x4.shared.b16 {%0,%1,%2,%3}, [%4];" \
        : "=r"(r0), "=r"(r1), "=r"(r2), "=r"(r3) : "r"(addr))

#define MMA16816(d, a, b)                                                      \
    asm volatile("mma.sync.aligned.m16n8k16.row.col.f32.f16.f16.f32 "          \
        "{%0,%1,%2,%3}, {%4,%5,%6,%7}, {%8,%9}, {%0,%1,%2,%3};\n"              \
        : "+f"((d)[0]), "+f"((d)[1]), "+f"((d)[2]), "+f"((d)[3])               \
        : "r"((a)[0]), "r"((a)[1]), "r"((a)[2]), "r"((a)[3]),                  \
          "r"((b)[0]), "r"((b)[1]))

// ---------------------------------------------------------------------------
// Fused prep kernel.
//   Blocks [0, WEFF_BLOCKS):            W_eff = (wq-zero)*scale + 2*B@A -> fp16
//   Blocks [WEFF_BLOCKS, +CONV_BLOCKS): x (fp32) -> fp16
// Both halves are DRAM-bound; fusing them into one wave overlaps the
// read-dominated wq stream with the read+write conv stream.
// ---------------------------------------------------------------------------
constexpr int WEFF_BO = 64, WEFF_BI = 256;
constexpr int WEFF_BLOCKS = (NN / WEFF_BO) * (KK / WEFF_BI);   // 64*16 = 1024
constexpr int CONV_BLOCKS = (int)((size_t)MM * KK / 8 / 256);  // 16384
constexpr int PREP_BLOCKS = WEFF_BLOCKS + CONV_BLOCKS;

__global__ void __launch_bounds__(256)
prep_kernel(const float4* __restrict__ x,
            const int* __restrict__ wq,
            const float* __restrict__ scale,
            const float* __restrict__ zero,
            const float* __restrict__ lA,
            const float* __restrict__ lB) {
    const int tid = threadIdx.x;

    if (blockIdx.x < (unsigned)WEFF_BLOCKS) {
        // ---------------- W_eff build ----------------
        __shared__ float sA[RR][WEFF_BI];    // lA tile   (16 KB)
        __shared__ float sB[WEFF_BO][RR];    // lB tile   (4 KB)
        __shared__ float sS[WEFF_BO], sZ[WEFF_BO];

        const int b  = blockIdx.x;
        const int i0 = (b % (KK / WEFF_BI)) * WEFF_BI;
        const int o0 = (b / (KK / WEFF_BI)) * WEFF_BO;

        for (int idx = tid; idx < RR * WEFF_BI; idx += 256) {
            int r = idx / WEFF_BI, i = idx % WEFF_BI;
            sA[r][i] = lA[(size_t)r * KK + i0 + i];
        }
        for (int idx = tid; idx < WEFF_BO * RR; idx += 256) {
            int o = idx / RR, r = idx % RR;
            sB[o][r] = lB[(size_t)(o0 + o) * RR + r];
        }
        if (tid < WEFF_BO) { sS[tid] = scale[o0 + tid]; sZ[tid] = zero[o0 + tid]; }
        __syncthreads();

        // 4 columns per step via int4 loads; LDS.128 on sA (conflict-free).
        constexpr int CH = WEFF_BI / 4;                  // 64 chunks per row
        for (int idx = tid; idx < WEFF_BO * CH; idx += 256) {
            const int o  = idx / CH;
            const int i4 = (idx % CH) * 4;
            const int4 wv = *reinterpret_cast<const int4*>(
                wq + (size_t)(o0 + o) * KK + i0 + i4);
            const float z = sZ[o], s = sS[o];
            float r0 = ((float)wv.x - z) * s;
            float r1 = ((float)wv.y - z) * s;
            float r2 = ((float)wv.z - z) * s;
            float r3 = ((float)wv.w - z) * s;
            float a0 = 0.f, a1 = 0.f, a2 = 0.f, a3 = 0.f;
            #pragma unroll
            for (int r = 0; r < RR; r++) {
                const float br = sB[o][r];
                const float4 av = *reinterpret_cast<const float4*>(&sA[r][i4]);
                a0 += br * av.x; a1 += br * av.y;
                a2 += br * av.z; a3 += br * av.w;
            }
            __half2 h01 = __floats2half2_rn(r0 + LORA_SCALING * a0,
                                            r1 + LORA_SCALING * a1);
            __half2 h23 = __floats2half2_rn(r2 + LORA_SCALING * a2,
                                            r3 + LORA_SCALING * a3);
            uint2 st;
            st.x = *reinterpret_cast<unsigned*>(&h01);
            st.y = *reinterpret_cast<unsigned*>(&h23);
            *reinterpret_cast<uint2*>(g_wh + (size_t)(o0 + o) * KK + i0 + i4) = st;
        }
    } else {
        // ---------------- x -> fp16 ----------------
        size_t i = (size_t)(blockIdx.x - WEFF_BLOCKS) * 256 + tid;
        float4 a = x[2 * i], b = x[2 * i + 1];
        __half2 h0 = __floats2half2_rn(a.x, a.y);
        __half2 h1 = __floats2half2_rn(a.z, a.w);
        __half2 h2 = __floats2half2_rn(b.x, b.y);
        __half2 h3 = __floats2half2_rn(b.z, b.w);
        uint4 o;
        o.x = *reinterpret_cast<unsigned*>(&h0);
        o.y = *reinterpret_cast<unsigned*>(&h1);
        o.z = *reinterpret_cast<unsigned*>(&h2);
        o.w = *reinterpret_cast<unsigned*>(&h3);
        ((uint4*)g_xh)[i] = o;
    }
}

// ---------------------------------------------------------------------------
// Kernel 3: fp16 mma.sync GEMM (byte-identical config to the 671.7us R12 run).
//   C[m,n] = sum_k xh[m,k]*wh[n,k] + bias[n]
// CTA tile 128x128x64, 3-stage cp.async, SW128 xor swizzle, ldmatrix frags.
// 8 warps: 4(M) x 2(N); warp tile 32x64 (2 m16-tiles x 8 n8-tiles). occ 2.
// ---------------------------------------------------------------------------
constexpr int BM = 128, BN = 128, BK = 64;     // halves; BK*2 = 128B rows (SW128)
constexpr int NSTAGES = 3;
constexpr int A_ST = BM * 128;                 // 16 KB per stage
constexpr int STG = 2 * A_ST;                  // 32 KB per stage (A + B)
constexpr int GEMM_SMEM = NSTAGES * STG + 128; // + align slack
constexpr int KT = KK / BK;                    // 64

__global__ void __launch_bounds__(256, 2)
gemm_fp16_kernel(const float* __restrict__ bias, float* __restrict__ C) {
    extern __shared__ char dsm[];
    const uint32_t tile = (smem_u32(dsm) + 127u) & ~127u;   // 128B-align

    const int tid  = threadIdx.x;
    const int warp = tid >> 5;
    const int lane = tid & 31;
    const int m0 = blockIdx.y * BM;
    const int n0 = blockIdx.x * BN;

    // ---- cp.async mapping: 2048 16B chunks / 256 threads = 8 each (4 A, 4 B)
    const __half* gA = g_xh + (size_t)m0 * KK;
    const __half* gB = g_wh + (size_t)n0 * KK;
    uint32_t soff[8];   // source offset in halves (row*KK + c16*8)
    uint32_t doff[8];   // dest byte offset within stage
    #pragma unroll
    for (int j = 0; j < 8; j++) {
        int c = tid + (j & 3) * 256;          // 0..1023
        int row = c >> 3, c16 = c & 7;
        soff[j] = (uint32_t)(row * KK + c16 * 8);
        doff[j] = (uint32_t)((j < 4 ? 0 : A_ST) + row * 128 + ((c16 ^ (row & 7)) << 4));
    }

    #define ISSUE_STAGE(kt_, s_) do {                                          \
        uint32_t base_ = tile + (s_) * STG;                                    \
        _Pragma("unroll")                                                      \
        for (int j = 0; j < 4; j++)                                            \
            CP_ASYNC16(base_ + doff[j], gA + soff[j] + (kt_) * BK);            \
        _Pragma("unroll")                                                      \
        for (int j = 4; j < 8; j++)                                            \
            CP_ASYNC16(base_ + doff[j], gB + soff[j] + (kt_) * BK);            \
        CP_COMMIT();                                                           \
    } while (0)

    // ---- warp/fragment geometry ----
    const int wm = (warp & 3) * 32;        // 4 warps along M
    const int wn = (warp >> 2) * 64;       // 2 warps along N
    const int gid = lane >> 2;             // 0..7
    const int tig = lane & 3;              // 0..3
    const int l7  = lane & 7;

    // ldmatrix per-lane row byte-offsets (swizzle chunk added per k-step)
    uint32_t a_row[2];
    #pragma unroll
    for (int mi = 0; mi < 2; mi++)
        a_row[mi] = (uint32_t)((wm + mi * 16 + (lane & 15)) * 128);
    const uint32_t a_cx = (uint32_t)(lane >> 4);        // chunk delta 0/1
    uint32_t b_row[4];
    #pragma unroll
    for (int ng = 0; ng < 4; ng++)
        b_row[ng] = (uint32_t)((wn + ng * 16 + l7 + ((lane >> 4) << 3)) * 128);
    const uint32_t b_cx = (uint32_t)((lane >> 3) & 1);  // chunk delta 0/1

    float acc[2][8][4];
    #pragma unroll
    for (int a = 0; a < 2; a++)
        #pragma unroll
        for (int b = 0; b < 8; b++)
            #pragma unroll
            for (int c = 0; c < 4; c++) acc[a][b][c] = 0.f;

    ISSUE_STAGE(0, 0);
    ISSUE_STAGE(1, 1);

    int s = 0;
    for (int kt = 0; kt < KT; kt++) {
        CP_WAIT(1);                       // oldest pending group (stage kt) done
        __syncthreads();                  // also fences reuse of stage (kt-1)%3
        if (kt + 2 < KT) {
            int sn = s + 2; if (sn >= NSTAGES) sn -= NSTAGES;
            ISSUE_STAGE(kt + 2, sn);
        }

        const uint32_t sA = tile + s * STG;
        const uint32_t sB = sA + A_ST;

        #pragma unroll
        for (int ks = 0; ks < 4; ks++) {          // 4 x k16 per BK=64
            const uint32_t kc = (uint32_t)(ks * 2);
            uint32_t af[2][4], bf[8][2];
            #pragma unroll
            for (int mi = 0; mi < 2; mi++) {
                uint32_t addr = sA + a_row[mi] + (((kc + a_cx) ^ l7) << 4);
                LDMATRIX_X4(af[mi][0], af[mi][1], af[mi][2], af[mi][3], addr);
            }
            #pragma unroll
            for (int ng = 0; ng < 4; ng++) {
                uint32_t addr = sB + b_row[ng] + (((kc + b_cx) ^ l7) << 4);
                LDMATRIX_X4(bf[2 * ng][0], bf[2 * ng][1],
                            bf[2 * ng + 1][0], bf[2 * ng + 1][1], addr);
            }
            #pragma unroll
            for (int mi = 0; mi < 2; mi++)
                #pragma unroll
                for (int ni = 0; ni < 8; ni++)
                    MMA16816(acc[mi][ni], af[mi], bf[ni]);
        }
        if (++s == NSTAGES) s = 0;
    }

    // ---- epilogue: + bias, float2 stores ----
    #pragma unroll
    for (int mi = 0; mi < 2; mi++) {
        const int row0 = m0 + wm + mi * 16 + gid;
        #pragma unroll
        for (int ni = 0; ni < 8; ni++) {
            const int col = n0 + wn + ni * 8 + tig * 2;
            const float b0 = __ldg(bias + col);
            const float b1 = __ldg(bias + col + 1);
            float2 v0 = make_float2(acc[mi][ni][0] + b0, acc[mi][ni][1] + b1);
            float2 v1 = make_float2(acc[mi][ni][2] + b0, acc[mi][ni][3] + b1);
            *(float2*)(C + (size_t)row0 * NN + col)       = v0;
            *(float2*)(C + (size_t)(row0 + 8) * NN + col) = v1;
        }
    }
    #undef ISSUE_STAGE
}

// ---------------------------------------------------------------------------
// Launch
// ---------------------------------------------------------------------------
extern "C" void kernel_launch(void* const* d_in, const int* in_sizes, int n_in,
                              void* d_out, int out_size) {
    const float* x     = (const float*)d_in[0];
    const int*   wq    = (const int*)  d_in[1];
    const float* scale = (const float*)d_in[2];
    const float* zero  = (const float*)d_in[3];
    const float* lA    = (const float*)d_in[4];
    const float* lB    = (const float*)d_in[5];
    const float* bias  = (const float*)d_in[6];
    float* out = (float*)d_out;

    cudaFuncSetAttribute(gemm_fp16_kernel,
                         cudaFuncAttributeMaxDynamicSharedMemorySize, GEMM_SMEM);

    // 1) fused prep: W_eff build + x->fp16 in one wave
    prep_kernel<<<PREP_BLOCKS, 256>>>((const float4*)x, wq, scale, zero, lA, lB);

    // 2) fp16 tensor-core GEMM + bias
    {
        dim3 grid(NN / BN, MM / BM);   // (32, 64)
        gemm_fp16_kernel<<<grid, 256, GEMM_SMEM>>>(bias, out);
    }
}